// round 1
// baseline (speedup 1.0000x reference)
#include <cuda_runtime.h>
#include <math.h>

// Problem constants
constexpr int cNB   = 512;
constexpr int cMS   = 8;
constexpr int cT    = 64;
constexpr int cIN   = 360;
constexpr int cH    = 230;
constexpr int cOUT  = 53;
constexpr int cENT  = 8;
constexpr int cB    = cNB * cMS;     // 4096
constexpr int c3H   = 3 * cH;        // 690
constexpr int c2H   = 2 * cH;        // 460
constexpr size_t cTB = (size_t)cT * cB;   // 262144

// ---------------------------------------------------------------------------
// Scratch (static device globals; no allocations allowed)
// ---------------------------------------------------------------------------
static __device__ float g_xg_f[(size_t)cT * cB * c3H];  // [T][B][3H]
static __device__ float g_xg_r[(size_t)cT * cB * c3H];
static __device__ float g_out [(size_t)cT * cB * c2H];  // [T][B][2H] concat(hf,hr)
static __device__ float g_u   [(size_t)cT * cB * c2H];  // word attention tanh(out@Ww+b)
static __device__ float g_h   [2][2][(size_t)cB * cH];  // [dir][pingpong][B*H]
static __device__ float g_score[(size_t)cB * cT];       // [B][T]
static __device__ float g_alpha[(size_t)cB * cT];       // [B][T]
static __device__ float g_wv  [(size_t)cB * c2H];       // word_vec [B][2H]
static __device__ float g_u2  [(size_t)cB * c2H];
static __device__ float g_s2  [cB];
static __device__ float g_sent[(size_t)cNB * c2H];

// ---------------------------------------------------------------------------
// Utility kernels
// ---------------------------------------------------------------------------
__global__ void zero_h_kernel() {
    float* p = &g_h[0][0][0];
    size_t n = (size_t)4 * cB * cH;
    size_t stride = (size_t)gridDim.x * blockDim.x;
    for (size_t i = (size_t)blockIdx.x * blockDim.x + threadIdx.x; i < n; i += stride)
        p[i] = 0.f;
}

__global__ void zero_out_kernel(float* p, int n) {
    int i = blockIdx.x * blockDim.x + threadIdx.x;
    if (i < n) p[i] = 0.f;
}

// ---------------------------------------------------------------------------
// Generic tiled SGEMM. SEL selects source/dest buffers and layout:
//  SEL 0: C=g_xg_f, A=param (bag), B is [N][K] ("TN"), no act, row remap (b*T+t)->(t*B+b)
//  SEL 1: C=g_xg_r, same
//  SEL 2: C=g_u,  A=g_out, B is [K][N] ("NN"), tanh epilogue, no remap
//  SEL 3: C=g_u2, A=g_wv,  B is [K][N], tanh, no remap
// C[m][n] = act( sum_k A[m][k] * B(k,n) + bias[n] )
// ---------------------------------------------------------------------------
template <int SEL>
__device__ __forceinline__ const float* srcA(const float* Ap) {
    if (SEL <= 1) return Ap;
    if (SEL == 2) return g_out;
    return g_wv;
}
template <int SEL>
__device__ __forceinline__ float* dstC() {
    if (SEL == 0) return g_xg_f;
    if (SEL == 1) return g_xg_r;
    if (SEL == 2) return g_u;
    return g_u2;
}

template <int SEL>
__global__ void __launch_bounds__(256) sgemm_kernel(
    const float* __restrict__ Ap, int lda,
    const float* __restrict__ Bw, int ldb,
    const float* __restrict__ bias,
    int M, int N, int K, int ldc)
{
    constexpr bool BNN   = (SEL >= 2);   // B stored [K][N] if true else [N][K]
    constexpr bool ACT   = (SEL >= 2);   // tanh
    constexpr bool REMAP = (SEL <= 1);   // C row remap (b*T+t) -> (t*B+b)

    const float* __restrict__ A = srcA<SEL>(Ap);
    float* __restrict__ C = dstC<SEL>();

    __shared__ float As[16][128];
    __shared__ float Bs[16][64];

    const int m0 = blockIdx.y * 128;
    const int n0 = blockIdx.x * 64;
    const int tid = threadIdx.x;
    const int ty = tid >> 4;   // 0..15, 8 rows each
    const int tx = tid & 15;   // 0..15, 4 cols each

    float acc[8][4] = {};

    for (int k0 = 0; k0 < K; k0 += 16) {
        // --- load A tile: 128 rows x 16 k ---
        {
            int ar = tid >> 1;
            int ac0 = (tid & 1) * 8;
            bool mval = (m0 + ar) < M;
            const float* ap = A + (size_t)(m0 + ar) * lda + k0 + ac0;
            #pragma unroll
            for (int q = 0; q < 8; q++) {
                int kk = ac0 + q;
                As[kk][ar] = (mval && (k0 + kk) < K) ? ap[q] : 0.f;
            }
        }
        // --- load B tile: 16 k x 64 n ---
        if (BNN) {
            #pragma unroll
            for (int q = 0; q < 4; q++) {
                int idx = q * 256 + tid;
                int kk = idx >> 6, n = idx & 63;
                float v = 0.f;
                if ((k0 + kk) < K && (n0 + n) < N)
                    v = Bw[(size_t)(k0 + kk) * ldb + n0 + n];
                Bs[kk][n] = v;
            }
        } else {
            int br = tid >> 2;
            int bc0 = (tid & 3) * 4;
            #pragma unroll
            for (int q = 0; q < 4; q++) {
                int kk = bc0 + q;
                float v = 0.f;
                if ((n0 + br) < N && (k0 + kk) < K)
                    v = Bw[(size_t)(n0 + br) * ldb + k0 + kk];
                Bs[kk][br] = v;
            }
        }
        __syncthreads();

        #pragma unroll
        for (int kk = 0; kk < 16; kk++) {
            float a[8], b[4];
            #pragma unroll
            for (int i = 0; i < 8; i++) a[i] = As[kk][ty * 8 + i];
            #pragma unroll
            for (int j = 0; j < 4; j++) b[j] = Bs[kk][tx * 4 + j];
            #pragma unroll
            for (int i = 0; i < 8; i++)
                #pragma unroll
                for (int j = 0; j < 4; j++)
                    acc[i][j] += a[i] * b[j];
        }
        __syncthreads();
    }

    #pragma unroll
    for (int i = 0; i < 8; i++) {
        int m = m0 + ty * 8 + i;
        if (m >= M) continue;
        size_t crow;
        if (REMAP) {
            // m = b*T + t  ->  crow = t*B + b   (T=64, B=4096)
            crow = (size_t)(m & (cT - 1)) * cB + (m >> 6);
        } else {
            crow = (size_t)m;
        }
        #pragma unroll
        for (int j = 0; j < 4; j++) {
            int n = n0 + tx * 4 + j;
            if (n < N) {
                float v = acc[i][j] + bias[n];
                if (ACT) v = tanhf(v);
                C[crow * ldc + n] = v;
            }
        }
    }
}

// ---------------------------------------------------------------------------
// One GRU time step, both directions (blockIdx.z). Tile 64 batch x 32 hidden.
// hg = h @ W_hh^T + b_hh ; gates ; h2 -> h_out and g_out[t][b][dir*H + j]
// ---------------------------------------------------------------------------
__global__ void __launch_bounds__(256) gru_step_kernel(
    const float* __restrict__ Whh_f, const float* __restrict__ Whh_r,
    const float* __restrict__ bhh_f, const float* __restrict__ bhh_r,
    int s)
{
    const int dir = blockIdx.z;
    const int t = dir ? (cT - 1 - s) : s;
    const float* __restrict__ xg  = dir ? g_xg_r : g_xg_f;
    const float* __restrict__ Whh = dir ? Whh_r : Whh_f;
    const float* __restrict__ bhh = dir ? bhh_r : bhh_f;
    const float* __restrict__ h_in  = g_h[dir][s & 1];
    float* __restrict__ h_out       = g_h[dir][(s & 1) ^ 1];

    const int b0 = blockIdx.x * 64;
    const int j0 = blockIdx.y * 32;
    const int tid = threadIdx.x;
    const int ty = tid >> 4;   // 0..15 -> 4 batch rows each
    const int tx = tid & 15;   // 0..15 -> 2 hidden cols each

    __shared__ float Hs[8][64];
    __shared__ float Ws[3][8][32];

    float acc[3][4][2] = {};

    for (int k0 = 0; k0 < cH; k0 += 8) {
        {
            int hr = tid >> 2;
            int hc0 = (tid & 3) * 2;
            #pragma unroll
            for (int q = 0; q < 2; q++) {
                int kk = hc0 + q;
                Hs[kk][hr] = ((k0 + kk) < cH) ? h_in[(size_t)(b0 + hr) * cH + k0 + kk] : 0.f;
            }
        }
        #pragma unroll
        for (int q = 0; q < 3; q++) {
            int idx = q * 256 + tid;
            int jrow = idx >> 3, kk = idx & 7;
            int g = jrow >> 5, j = jrow & 31;
            float v = 0.f;
            if ((j0 + j) < cH && (k0 + kk) < cH)
                v = Whh[(size_t)(g * cH + j0 + j) * cH + k0 + kk];
            Ws[g][kk][j] = v;
        }
        __syncthreads();

        #pragma unroll
        for (int kk = 0; kk < 8; kk++) {
            float hv[4];
            #pragma unroll
            for (int i = 0; i < 4; i++) hv[i] = Hs[kk][ty * 4 + i];
            float w[3][2];
            #pragma unroll
            for (int g = 0; g < 3; g++)
                #pragma unroll
                for (int j = 0; j < 2; j++) w[g][j] = Ws[g][kk][tx * 2 + j];
            #pragma unroll
            for (int g = 0; g < 3; g++)
                #pragma unroll
                for (int i = 0; i < 4; i++)
                    #pragma unroll
                    for (int j = 0; j < 2; j++)
                        acc[g][i][j] += hv[i] * w[g][j];
        }
        __syncthreads();
    }

    #pragma unroll
    for (int i = 0; i < 4; i++) {
        const int b = b0 + ty * 4 + i;
        const float* xrow = xg + ((size_t)t * cB + b) * c3H;
        #pragma unroll
        for (int j = 0; j < 2; j++) {
            const int jg = j0 + tx * 2 + j;
            if (jg >= cH) continue;
            float r = 1.f / (1.f + expf(-(xrow[jg]        + acc[0][i][j] + bhh[jg])));
            float z = 1.f / (1.f + expf(-(xrow[cH + jg]   + acc[1][i][j] + bhh[cH + jg])));
            float n = tanhf(xrow[2 * cH + jg] + r * (acc[2][i][j] + bhh[2 * cH + jg]));
            float hold = h_in[(size_t)b * cH + jg];
            float h2 = (1.f - z) * n + z * hold;
            h_out[(size_t)b * cH + jg] = h2;
            g_out[((size_t)t * cB + b) * c2H + dir * cH + jg] = h2;
        }
    }
}

// ---------------------------------------------------------------------------
// score[row] = u_row . proj   (warp per row)
//  SEL2=0: U=g_u  (rows (t,b) = t*B+b), out g_score[b*T+t]
//  SEL2=1: U=g_u2 (rows b),             out g_s2[b]
// ---------------------------------------------------------------------------
template <int SEL2>
__global__ void rowdot_kernel(const float* __restrict__ proj, int M, int N) {
    int row = blockIdx.x * 8 + (threadIdx.x >> 5);
    if (row >= M) return;
    int lane = threadIdx.x & 31;
    const float* __restrict__ U = (SEL2 == 0) ? g_u : g_u2;
    const float* u = U + (size_t)row * N;
    float s = 0.f;
    for (int j = lane; j < N; j += 32) s += u[j] * proj[j];
    #pragma unroll
    for (int o = 16; o; o >>= 1) s += __shfl_xor_sync(0xffffffffu, s, o);
    if (lane == 0) {
        if (SEL2 == 0) {
            int tt = row >> 12;           // row / 4096
            int b  = row & (cB - 1);
            g_score[(size_t)b * cT + tt] = s;
        } else {
            g_s2[row] = s;
        }
    }
}

// softmax over T per batch element (warp per b, T=64)
__global__ void softmaxT_kernel() {
    int b = blockIdx.x * 8 + (threadIdx.x >> 5);
    int lane = threadIdx.x & 31;
    const float* s = g_score + (size_t)b * cT;
    float v0 = s[lane], v1 = s[lane + 32];
    float m = fmaxf(v0, v1);
    #pragma unroll
    for (int o = 16; o; o >>= 1) m = fmaxf(m, __shfl_xor_sync(0xffffffffu, m, o));
    float e0 = expf(v0 - m), e1 = expf(v1 - m);
    float sum = e0 + e1;
    #pragma unroll
    for (int o = 16; o; o >>= 1) sum += __shfl_xor_sync(0xffffffffu, sum, o);
    float inv = 1.f / sum;
    g_alpha[(size_t)b * cT + lane] = e0 * inv;
    g_alpha[(size_t)b * cT + lane + 32] = e1 * inv;
}

// word_vec[b][h] = sum_t alpha[b][t] * out[t][b][h]
__global__ void wordvec_kernel() {
    int b = blockIdx.y;
    int h = blockIdx.x * 128 + threadIdx.x;
    if (h >= c2H) return;
    const float* al = g_alpha + (size_t)b * cT;
    float s = 0.f;
    for (int t = 0; t < cT; t++)
        s += al[t] * g_out[((size_t)t * cB + b) * c2H + h];
    g_wv[(size_t)b * c2H + h] = s;
}

// per-doc-bag: beta = softmax over MS of s2; sent_vec = sum_ms beta*wv
__global__ void sentvec_kernel() {
    int nb = blockIdx.x;
    __shared__ float beta[cMS];
    if (threadIdx.x == 0) {
        float v[cMS];
        float m = -1e30f;
        for (int ms = 0; ms < cMS; ms++) { v[ms] = g_s2[nb * cMS + ms]; m = fmaxf(m, v[ms]); }
        float sum = 0.f;
        for (int ms = 0; ms < cMS; ms++) { v[ms] = expf(v[ms] - m); sum += v[ms]; }
        float inv = 1.f / sum;
        for (int ms = 0; ms < cMS; ms++) beta[ms] = v[ms] * inv;
    }
    __syncthreads();
    for (int h = threadIdx.x; h < c2H; h += blockDim.x) {
        float s = 0.f;
        #pragma unroll
        for (int ms = 0; ms < cMS; ms++)
            s += beta[ms] * g_wv[((size_t)nb * cMS + ms) * c2H + h];
        g_sent[(size_t)nb * c2H + h] = s;
    }
}

// fc + scatter into (DOCS, ENT, ENT, OUT)
__global__ void fc_scatter_kernel(const float* __restrict__ fcW,
                                  const float* __restrict__ fcb,
                                  const int* __restrict__ pairs,
                                  float* __restrict__ out)
{
    int nb = blockIdx.x;
    __shared__ float sv[c2H];
    for (int k = threadIdx.x; k < c2H; k += blockDim.x)
        sv[k] = g_sent[(size_t)nb * c2H + k];
    __syncthreads();
    int o = threadIdx.x;
    if (o < cOUT) {
        const float* w = fcW + (size_t)o * c2H;
        float s = fcb[o];
        for (int k = 0; k < c2H; k++) s += sv[k] * w[k];
        int d  = pairs[nb * 3 + 0];
        int e1 = pairs[nb * 3 + 1];
        int e2 = pairs[nb * 3 + 2];
        out[(((size_t)d * cENT + e1) * cENT + e2) * cOUT + o] = s;
    }
}

// ---------------------------------------------------------------------------
extern "C" void kernel_launch(void* const* d_in, const int* in_sizes, int n_in,
                              void* d_out, int out_size) {
    const float* bag   = (const float*)d_in[0];
    const float* Wihf  = (const float*)d_in[1];
    const float* Whhf  = (const float*)d_in[2];
    const float* bihf  = (const float*)d_in[3];
    const float* bhhf  = (const float*)d_in[4];
    const float* Wihr  = (const float*)d_in[5];
    const float* Whhr  = (const float*)d_in[6];
    const float* bihr  = (const float*)d_in[7];
    const float* bhhr  = (const float*)d_in[8];
    const float* Wword = (const float*)d_in[9];
    const float* bword = (const float*)d_in[10];
    const float* pjw   = (const float*)d_in[11];
    const float* Wsent = (const float*)d_in[12];
    const float* bsent = (const float*)d_in[13];
    const float* pjs   = (const float*)d_in[14];
    const float* fcW   = (const float*)d_in[15];
    const float* fcb   = (const float*)d_in[16];
    const int*   pairs = (const int*)d_in[17];
    float* out = (float*)d_out;

    // init: zero hidden states (h0 = 0) and the output tensor
    zero_h_kernel<<<2048, 256>>>();
    zero_out_kernel<<<(out_size + 255) / 256, 256>>>(out, out_size);

    // input projections: xg = x @ W_ih^T + b_ih   (M=T*B rows in (b,t) order,
    // remapped to [T][B][3H])
    {
        dim3 grid((c3H + 63) / 64, (int)(cTB / 128));
        sgemm_kernel<0><<<grid, 256>>>(bag, cIN, Wihf, cIN, bihf,
                                       (int)cTB, c3H, cIN, c3H);
        sgemm_kernel<1><<<grid, 256>>>(bag, cIN, Wihr, cIN, bihr,
                                       (int)cTB, c3H, cIN, c3H);
    }

    // GRU recurrence, 64 steps, both directions per launch
    {
        dim3 grid(cB / 64, (cH + 31) / 32, 2);
        for (int s = 0; s < cT; s++)
            gru_step_kernel<<<grid, 256>>>(Whhf, Whhr, bhhf, bhhr, s);
    }

    // word attention: u = tanh(out @ W_word + b_word); score = u . proj_word
    {
        dim3 grid((c2H + 63) / 64, (int)(cTB / 128));
        sgemm_kernel<2><<<grid, 256>>>(nullptr, c2H, Wword, c2H, bword,
                                       (int)cTB, c2H, c2H, c2H);
    }
    rowdot_kernel<0><<<(int)(cTB / 8), 256>>>(pjw, (int)cTB, c2H);
    softmaxT_kernel<<<cB / 8, 256>>>();
    {
        dim3 grid((c2H + 127) / 128, cB);
        wordvec_kernel<<<grid, 128>>>();
    }

    // sentence attention
    {
        dim3 grid((c2H + 63) / 64, cB / 128);
        sgemm_kernel<3><<<grid, 256>>>(nullptr, c2H, Wsent, c2H, bsent,
                                       cB, c2H, c2H, c2H);
    }
    rowdot_kernel<1><<<cB / 8, 256>>>(pjs, cB, c2H);
    sentvec_kernel<<<cNB, 128>>>();

    // fc + scatter
    fc_scatter_kernel<<<cNB, 64>>>(fcW, fcb, pairs, out);
}